// round 14
// baseline (speedup 1.0000x reference)
#include <cuda_runtime.h>
#include <cuda_fp16.h>
#include <cstdint>

// ---------------------------------------------------------------------------
// 3-layer GAT, N=50000 nodes, E=800000 edges.
// R14: R13 (best: 218us) + 4-bank aggregation gather (MLP 2->4 on the
//      latency-bound fh row gathers). Everything else identical.
// ---------------------------------------------------------------------------

#define NMAX 50000
#define EMAX 800000

__device__ float g_hA[NMAX * 128];
__device__ float g_hB[NMAX * 128];
__device__ float g_fh[NMAX * 128];   // used as __half[NMAX*128]
__device__ float g_el[NMAX * 2];
__device__ float g_er[NMAX * 2];
__device__ float g_Wc[128 * 128];
__device__ int   g_row[NMAX + 1];
__device__ int   g_cur[NMAX];
__device__ int   g_col[EMAX];
__device__ int   g_bsum[64];

__device__ __forceinline__ float lrelu(float v) { return v > 0.f ? v : 0.2f * v; }

__device__ __forceinline__ uint32_t f2tf32(float f) {
    uint32_t r;
    asm("cvt.rna.tf32.f32 %0, %1;" : "=r"(r) : "f"(f));
    return r;
}

__device__ __forceinline__ void mma_tf32(float c[4], const uint32_t a[4],
                                         const uint32_t b[2]) {
    asm volatile(
        "mma.sync.aligned.m16n8k8.row.col.f32.tf32.tf32.f32 "
        "{%0,%1,%2,%3}, {%4,%5,%6,%7}, {%8,%9}, {%0,%1,%2,%3};"
        : "+f"(c[0]), "+f"(c[1]), "+f"(c[2]), "+f"(c[3])
        : "r"(a[0]), "r"(a[1]), "r"(a[2]), "r"(a[3]), "r"(b[0]), "r"(b[1]));
}

namespace {
struct ForkRes {
    cudaStream_t s1;
    cudaEvent_t e0, e1, e2;
    ForkRes() {
        cudaStreamCreateWithFlags(&s1, cudaStreamNonBlocking);
        cudaEventCreateWithFlags(&e0, cudaEventDisableTiming);
        cudaEventCreateWithFlags(&e1, cudaEventDisableTiming);
        cudaEventCreateWithFlags(&e2, cudaEventDisableTiming);
    }
};
ForkRes g_fork;
}

// ---------------------------------------------------------------------------
// CSR build
// ---------------------------------------------------------------------------
__global__ void k_count(const int* __restrict__ dst, int* __restrict__ cnt, int E) {
    int e = blockIdx.x * blockDim.x + threadIdx.x;
    if (e < E) atomicAdd(&cnt[dst[e]], 1);
}
__global__ void k_bsum(const int* __restrict__ cnt, int* __restrict__ bsum, int N) {
    __shared__ int ws[32];
    int i = blockIdx.x * 1024 + threadIdx.x;
    int lane = threadIdx.x & 31, wid = threadIdx.x >> 5;
    int v = (i < N) ? cnt[i] : 0;
#pragma unroll
    for (int o = 16; o > 0; o >>= 1) v += __shfl_xor_sync(0xffffffffu, v, o);
    if (lane == 0) ws[wid] = v;
    __syncthreads();
    if (wid == 0) {
        int x = ws[lane];
#pragma unroll
        for (int o = 16; o > 0; o >>= 1) x += __shfl_xor_sync(0xffffffffu, x, o);
        if (lane == 0) bsum[blockIdx.x] = x;
    }
}
__global__ void k_bscan(int* __restrict__ bsum, int nb) {
    __shared__ int sh[64];
    int tid = threadIdx.x;
    int v = (tid < nb) ? bsum[tid] : 0;
    sh[tid] = v;
    __syncthreads();
#pragma unroll
    for (int o = 1; o < 64; o <<= 1) {
        int t = (tid >= o) ? sh[tid - o] : 0;
        __syncthreads();
        sh[tid] += t;
        __syncthreads();
    }
    if (tid < nb) bsum[tid] = sh[tid] - v;
}
__global__ void k_scan2(const int* __restrict__ cnt, const int* __restrict__ bsum,
                        int* __restrict__ row, int* __restrict__ cur, int N, int E) {
    __shared__ int ws[32];
    int i = blockIdx.x * 1024 + threadIdx.x;
    int lane = threadIdx.x & 31, wid = threadIdx.x >> 5;
    int v = (i < N) ? cnt[i] : 0;
    int x = v;
#pragma unroll
    for (int o = 1; o < 32; o <<= 1) {
        int t = __shfl_up_sync(0xffffffffu, x, o);
        if (lane >= o) x += t;
    }
    if (lane == 31) ws[wid] = x;
    __syncthreads();
    if (wid == 0) {
        int y = ws[lane];
#pragma unroll
        for (int o = 1; o < 32; o <<= 1) {
            int t = __shfl_up_sync(0xffffffffu, y, o);
            if (lane >= o) y += t;
        }
        ws[lane] = y;
    }
    __syncthreads();
    int excl = bsum[blockIdx.x] + (wid ? ws[wid - 1] : 0) + x - v;
    if (i < N) { row[i] = excl; cur[i] = excl; }
    if (i == 0) row[N] = E;
}
__global__ void k_scatter(const int* __restrict__ src, const int* __restrict__ dst,
                          int* __restrict__ cur, int* __restrict__ col, int E) {
    int e = blockIdx.x * blockDim.x + threadIdx.x;
    if (e >= E) return;
    int slot = atomicAdd(&cur[dst[e]], 1);
    col[slot] = src[e];
}
__global__ void k_wcat(const float* __restrict__ W2, const float* __restrict__ resW2,
                       float* __restrict__ Wc) {
    int i = blockIdx.x * blockDim.x + threadIdx.x;
    if (i >= 128 * 128) return;
    int k = i >> 7, j = i & 127;
    Wc[i] = (j < 64) ? W2[k * 64 + j] : resW2[k * 64 + (j - 64)];
}

// ---------------------------------------------------------------------------
// TF32 mma.sync GEMM + fused scores. stage ALIASES sW (dead after mainloop).
// ---------------------------------------------------------------------------
template <int K, int HS, bool SPLIT, bool EMB>
__global__ void __launch_bounds__(256)
k_mgemm(const float* __restrict__ A, const int* __restrict__ feats,
        const float* __restrict__ fv, const float* __restrict__ emb,
        const float* __restrict__ W,
        void* __restrict__ outh, float* __restrict__ out2,
        const float* __restrict__ al, const float* __restrict__ ar,
        float* __restrict__ el, float* __restrict__ er, int N) {
    extern __shared__ char smraw[];
    uint32_t* sW    = (uint32_t*)smraw;                    // K*132
    uint32_t* sA    = (uint32_t*)(smraw + K * 132 * 4);    // 64*(K+4)
    float*    stage = (float*)smraw;                       // aliases sW (64*132)
    constexpr int SAS = K + 4;

    const int tid = threadIdx.x;
    const int wid = tid >> 5, lane = tid & 31;
    const int g = lane >> 2, t = lane & 3;
    const int row0 = blockIdx.x * 64;
    const int wRow = (wid >> 2) * 32, wCol = (wid & 3) * 32;

    for (int i = tid; i < K * 32; i += 256) {
        int k = i >> 5, c4 = i & 31;
        float4 v = *(const float4*)&W[k * 128 + c4 * 4];
        uint4 u;
        u.x = f2tf32(v.x); u.y = f2tf32(v.y); u.z = f2tf32(v.z); u.w = f2tf32(v.w);
        *(uint4*)&sW[k * 132 + c4 * 4] = u;
    }
    constexpr int C4 = K / 4;
    for (int i = tid; i < 64 * C4; i += 256) {
        int r = i / C4, c4 = i % C4, rr = row0 + r;
        float4 v = make_float4(0.f, 0.f, 0.f, 0.f);
        if (rr < N) {
            if (EMB) {
                float s = fv[rr];
                v = *(const float4*)&emb[(long long)feats[rr] * 64 + c4 * 4];
                v.x *= s; v.y *= s; v.z *= s; v.w *= s;
            } else {
                v = *(const float4*)&A[(size_t)rr * K + c4 * 4];
            }
        }
        uint4 u;
        u.x = f2tf32(v.x); u.y = f2tf32(v.y); u.z = f2tf32(v.z); u.w = f2tf32(v.w);
        *(uint4*)&sA[r * SAS + c4 * 4] = u;
    }
    __syncthreads();

    float c[2][4][4];
#pragma unroll
    for (int mf = 0; mf < 2; mf++)
#pragma unroll
        for (int nf = 0; nf < 4; nf++)
#pragma unroll
            for (int i = 0; i < 4; i++) c[mf][nf][i] = 0.f;

#pragma unroll
    for (int ks = 0; ks < K / 8; ks++) {
        const int k0 = ks * 8;
        uint32_t a[2][4];
#pragma unroll
        for (int mf = 0; mf < 2; mf++) {
            int rb = wRow + mf * 16;
            a[mf][0] = sA[(rb + g)     * SAS + k0 + t];
            a[mf][1] = sA[(rb + g + 8) * SAS + k0 + t];
            a[mf][2] = sA[(rb + g)     * SAS + k0 + t + 4];
            a[mf][3] = sA[(rb + g + 8) * SAS + k0 + t + 4];
        }
        uint32_t b[4][2];
#pragma unroll
        for (int nf = 0; nf < 4; nf++) {
            int cc = wCol + nf * 8 + g;
            b[nf][0] = sW[(k0 + t)     * 132 + cc];
            b[nf][1] = sW[(k0 + t + 4) * 132 + cc];
        }
#pragma unroll
        for (int mf = 0; mf < 2; mf++)
#pragma unroll
            for (int nf = 0; nf < 4; nf++)
                mma_tf32(c[mf][nf], a[mf], b[nf]);
    }
    __syncthreads();   // sW dead; stage takes over

#pragma unroll
    for (int mf = 0; mf < 2; mf++) {
#pragma unroll
        for (int nf = 0; nf < 4; nf++) {
            int ra = wRow + mf * 16 + g;
            int cc = wCol + nf * 8 + t * 2;
            *(float2*)&stage[ra * 132 + cc]       = make_float2(c[mf][nf][0], c[mf][nf][1]);
            *(float2*)&stage[(ra + 8) * 132 + cc] = make_float2(c[mf][nf][2], c[mf][nf][3]);
        }
    }
    __syncthreads();

    float4 a4 = make_float4(0.f, 0.f, 0.f, 0.f);
    float4 r4 = make_float4(0.f, 0.f, 0.f, 0.f);
    if (lane * 4 < HS * 64) {
        a4 = *(const float4*)&al[lane * 4];
        r4 = *(const float4*)&ar[lane * 4];
    }
    __half* fhh = (__half*)outh;
#pragma unroll
    for (int q = 0; q < 8; q++) {
        int r = wid * 8 + q;
        int rr = row0 + r;
        float4 f = *(const float4*)&stage[r * 132 + lane * 4];
        float sl = f.x * a4.x + f.y * a4.y + f.z * a4.z + f.w * a4.w;
        float sr = f.x * r4.x + f.y * r4.y + f.z * r4.z + f.w * r4.w;
#pragma unroll
        for (int off = 8; off > 0; off >>= 1) {
            sl += __shfl_xor_sync(0xffffffffu, sl, off);
            sr += __shfl_xor_sync(0xffffffffu, sr, off);
        }
        int h = lane >> 4;
        if ((lane & 15) == 0 && h < HS && rr < N) {
            el[rr * HS + h] = sl;
            er[rr * HS + h] = sr;
        }
        if (rr < N) {
            __half2 ha = __float22half2_rn(make_float2(f.x, f.y));
            __half2 hb = __float22half2_rn(make_float2(f.z, f.w));
            uint2 u;
            u.x = *(uint32_t*)&ha; u.y = *(uint32_t*)&hb;
            if (SPLIT) {
                if (lane < 16) *(uint2*)(fhh + (size_t)rr * 64 + lane * 4) = u;
                else           *(float4*)&out2[(size_t)rr * 64 + lane * 4 - 64] = f;
            } else {
                *(uint2*)(fhh + (size_t)rr * 128 + lane * 4) = u;
            }
        }
    }
}

// ---------------------------------------------------------------------------
// Aggregation: warp per dst node; fp16 fh rows; L = O/8 lanes per row
// (uint4 per lane), G = 32/L edges in parallel; 4 banks (MLP 4).
// Out-of-range source lanes broadcast p=0 -> contribute nothing.
// ---------------------------------------------------------------------------
template <int O, int H, bool ELU>
__global__ void __launch_bounds__(256)
k_aggr(const int* __restrict__ row, const int* __restrict__ col,
       const float* __restrict__ el, const float* __restrict__ er,
       const void* __restrict__ fhv, const float* __restrict__ bias,
       const float* __restrict__ res, float* __restrict__ out, int N) {
    constexpr int L = O / 8;     // 16 (O=128) or 8 (O=64)
    constexpr int G = 32 / L;    // 2 or 4
    const unsigned FULL = 0xffffffffu;
    int w    = (blockIdx.x * blockDim.x + threadIdx.x) >> 5;
    int lane = threadIdx.x & 31;
    if (w >= N) return;
    const int grp = lane / L, sub = lane % L;
    const int c0 = sub * 8;
    const bool topHead = (H == 2) && (c0 >= 64);
    const __half* fhh = (const __half*)fhv;

    const float er0 = er[w * H + 0];
    const float er1 = (H == 2) ? er[w * H + 1] : 0.f;
    const int e0 = row[w], e1 = row[w + 1];

    float den0 = 0.f, den1 = 0.f;
    float acc[4][8];
#pragma unroll
    for (int b = 0; b < 4; b++)
#pragma unroll
        for (int i = 0; i < 8; i++) acc[b][i] = 0.f;

    for (int base = e0; base < e1; base += 32) {
        int idx = base + lane;
        bool valid = idx < e1;
        int s_l = valid ? col[idx] : 0;
        float p0_l = 0.f, p1_l = 0.f;
        if (valid) {
            if (H == 2) {
                float2 ev = *(const float2*)&el[s_l * 2];
                p0_l = __expf(lrelu(ev.x + er0));
                p1_l = __expf(lrelu(ev.y + er1));
                den0 += p0_l; den1 += p1_l;
            } else {
                p0_l = __expf(lrelu(el[s_l] + er0));
                den0 += p0_l;
            }
        }
        int n = min(32, e1 - base);
        for (int j = 0; j < n; j += 4 * G) {
#pragma unroll
            for (int b = 0; b < 4; b++) {
                int srcLane = j + b * G + grp;   // <=31 by construction
                int   s  = __shfl_sync(FULL, s_l,  srcLane);
                float pa = __shfl_sync(FULL, p0_l, srcLane);
                float p;
                if (H == 2) {
                    float pb = __shfl_sync(FULL, p1_l, srcLane);
                    p = topHead ? pb : pa;
                } else p = pa;
                uint4 u = *(const uint4*)(fhh + (size_t)s * O + c0);
                float2 f0 = __half22float2(*(__half2*)&u.x);
                float2 f1 = __half22float2(*(__half2*)&u.y);
                float2 f2 = __half22float2(*(__half2*)&u.z);
                float2 f3 = __half22float2(*(__half2*)&u.w);
                acc[b][0] += p * f0.x; acc[b][1] += p * f0.y;
                acc[b][2] += p * f1.x; acc[b][3] += p * f1.y;
                acc[b][4] += p * f2.x; acc[b][5] += p * f2.y;
                acc[b][6] += p * f3.x; acc[b][7] += p * f3.y;
            }
        }
    }

#pragma unroll
    for (int o = 16; o > 0; o >>= 1) {
        den0 += __shfl_xor_sync(FULL, den0, o);
        if (H == 2) den1 += __shfl_xor_sync(FULL, den1, o);
    }
    float sum[8];
#pragma unroll
    for (int i = 0; i < 8; i++) {
        float v = (acc[0][i] + acc[1][i]) + (acc[2][i] + acc[3][i]);
#pragma unroll
        for (int o = L; o < 32; o <<= 1) v += __shfl_xor_sync(FULL, v, o);
        sum[i] = v;
    }

    if (grp == 0) {
        float den = topHead ? den1 : den0;
        float inv = 1.f / fmaxf(den, 1e-9f);
        float4 bva = *(const float4*)&bias[c0];
        float4 bvb = *(const float4*)&bias[c0 + 4];
        float4 ra = make_float4(0.f, 0.f, 0.f, 0.f), rb = ra;
        if (res) {
            ra = *(const float4*)&res[(size_t)w * O + c0];
            rb = *(const float4*)&res[(size_t)w * O + c0 + 4];
        }
        float o8[8];
        o8[0] = sum[0] * inv + bva.x + ra.x;
        o8[1] = sum[1] * inv + bva.y + ra.y;
        o8[2] = sum[2] * inv + bva.z + ra.z;
        o8[3] = sum[3] * inv + bva.w + ra.w;
        o8[4] = sum[4] * inv + bvb.x + rb.x;
        o8[5] = sum[5] * inv + bvb.y + rb.y;
        o8[6] = sum[6] * inv + bvb.z + rb.z;
        o8[7] = sum[7] * inv + bvb.w + rb.w;
        if (ELU) {
#pragma unroll
            for (int i = 0; i < 8; i++)
                o8[i] = o8[i] > 0.f ? o8[i] : (__expf(o8[i]) - 1.f);
        }
        *(float4*)&out[(size_t)w * O + c0]     = make_float4(o8[0], o8[1], o8[2], o8[3]);
        *(float4*)&out[(size_t)w * O + c0 + 4] = make_float4(o8[4], o8[5], o8[6], o8[7]);
    }
}

// ---------------------------------------------------------------------------
extern "C" void kernel_launch(void* const* d_in, const int* in_sizes, int n_in,
                              void* d_out, int out_size) {
    const int*   feats = (const int*)  d_in[0];
    const float* fv    = (const float*)d_in[1];
    const int*   src   = (const int*)  d_in[2];
    const int*   dst   = (const int*)  d_in[3];
    const float* emb   = (const float*)d_in[4];
    const float* W0    = (const float*)d_in[5];
    const float* al0   = (const float*)d_in[6];
    const float* ar0   = (const float*)d_in[7];
    const float* b0    = (const float*)d_in[8];
    const float* W1    = (const float*)d_in[9];
    const float* al1   = (const float*)d_in[10];
    const float* ar1   = (const float*)d_in[11];
    const float* b1    = (const float*)d_in[12];
    const float* W2    = (const float*)d_in[13];
    const float* al2   = (const float*)d_in[14];
    const float* ar2   = (const float*)d_in[15];
    const float* b2    = (const float*)d_in[16];
    const float* resW2 = (const float*)d_in[17];
    float* out = (float*)d_out;

    const int N = in_sizes[0] / 8;
    const int E = in_sizes[2];

    float *hA, *hB, *fh, *el, *er, *Wc;
    int *row, *cur, *col, *bsum;
    cudaGetSymbolAddress((void**)&hA,   g_hA);
    cudaGetSymbolAddress((void**)&hB,   g_hB);
    cudaGetSymbolAddress((void**)&fh,   g_fh);
    cudaGetSymbolAddress((void**)&el,   g_el);
    cudaGetSymbolAddress((void**)&er,   g_er);
    cudaGetSymbolAddress((void**)&Wc,   g_Wc);
    cudaGetSymbolAddress((void**)&row,  g_row);
    cudaGetSymbolAddress((void**)&cur,  g_cur);
    cudaGetSymbolAddress((void**)&col,  g_col);
    cudaGetSymbolAddress((void**)&bsum, g_bsum);

    const int TB = 256;
    const int gB = (N + 63) / 64;
    const int aggrBlocks = (N * 32 + TB - 1) / TB;
    const int nb = (N + 1023) / 1024;

    const int SM64  = 64 * 132 * 4  + 64 * (64 + 4)  * 4;   // 51200
    const int SM128 = 128 * 132 * 4 + 64 * (128 + 4) * 4;   // 101376
    cudaFuncSetAttribute(k_mgemm<64, 2, false, true>,
                         cudaFuncAttributeMaxDynamicSharedMemorySize, SM64);
    cudaFuncSetAttribute(k_mgemm<128, 2, false, false>,
                         cudaFuncAttributeMaxDynamicSharedMemorySize, SM128);
    cudaFuncSetAttribute(k_mgemm<128, 1, true, false>,
                         cudaFuncAttributeMaxDynamicSharedMemorySize, SM128);

    cudaStream_t s1 = g_fork.s1;

    // fork: CSR build on s1; GEMM0 (fused embedding) on main
    cudaEventRecord(g_fork.e0, 0);
    cudaStreamWaitEvent(s1, g_fork.e0, 0);

    cudaMemsetAsync(cur, 0, (size_t)N * sizeof(int), s1);
    k_count  <<<(E + TB - 1) / TB, TB, 0, s1>>>(dst, cur, E);
    k_bsum   <<<nb, 1024, 0, s1>>>(cur, bsum, N);
    k_bscan  <<<1, 64, 0, s1>>>(bsum, nb);
    k_scan2  <<<nb, 1024, 0, s1>>>(cur, bsum, row, cur, N, E);
    k_scatter<<<(E + TB - 1) / TB, TB, 0, s1>>>(src, dst, cur, col, E);
    cudaEventRecord(g_fork.e1, s1);              // gates aggr0
    k_wcat<<<(128 * 128 + TB - 1) / TB, TB, 0, s1>>>(W2, resW2, Wc);
    cudaEventRecord(g_fork.e2, s1);              // gates GEMM2

    // Layer 0 GEMM with fused embedding (main)
    k_mgemm<64, 2, false, true><<<gB, 256, SM64>>>(
        nullptr, feats, fv, emb, W0, fh, nullptr, al0, ar0, el, er, N);

    cudaStreamWaitEvent(0, g_fork.e1, 0);

    // Layer 0 aggregation -> hB (fp32)
    k_aggr<128, 2, true><<<aggrBlocks, TB>>>(row, col, el, er, fh, b0, nullptr, hB, N);

    // Layer 1
    k_mgemm<128, 2, false, false><<<gB, 256, SM128>>>(
        hB, nullptr, nullptr, nullptr, W1, fh, nullptr, al1, ar1, el, er, N);
    k_aggr<128, 2, true><<<aggrBlocks, TB>>>(row, col, el, er, fh, b1, hB, hA, N);

    // Layer 2: combined [W2|resW2]; fh(half, cols 0-63) + residual hB(f32)
    cudaStreamWaitEvent(0, g_fork.e2, 0);
    k_mgemm<128, 1, true, false><<<gB, 256, SM128>>>(
        hA, nullptr, nullptr, nullptr, Wc, fh, hB, al2, ar2, el, er, N);
    k_aggr<64, 1, false><<<aggrBlocks, TB>>>(row, col, el, er, fh, b2, hB, out, N);
}

// round 15
// speedup vs baseline: 1.0834x; 1.0834x over previous
#include <cuda_runtime.h>
#include <cuda_fp16.h>
#include <cstdint>

// ---------------------------------------------------------------------------
// 3-layer GAT, N=50000 nodes, E=800000 edges.
// R15: R13 (best: 218us) with the CSR scan collapsed to ONE kernel via
//      decoupled lookback (49 co-resident blocks; state zeroed by k_count).
//      Aggregation reverted to R13's exact 2-bank version.
// ---------------------------------------------------------------------------

#define NMAX 50000
#define EMAX 800000

__device__ float g_hA[NMAX * 128];
__device__ float g_hB[NMAX * 128];
__device__ float g_fh[NMAX * 128];   // used as __half[NMAX*128]
__device__ float g_el[NMAX * 2];
__device__ float g_er[NMAX * 2];
__device__ float g_Wc[128 * 128];
__device__ int   g_row[NMAX + 1];
__device__ int   g_cur[NMAX];
__device__ int   g_col[EMAX];
__device__ unsigned long long g_state[64];   // lookback: value | flag

__device__ __forceinline__ float lrelu(float v) { return v > 0.f ? v : 0.2f * v; }

__device__ __forceinline__ uint32_t f2tf32(float f) {
    uint32_t r;
    asm("cvt.rna.tf32.f32 %0, %1;" : "=r"(r) : "f"(f));
    return r;
}

__device__ __forceinline__ void mma_tf32(float c[4], const uint32_t a[4],
                                         const uint32_t b[2]) {
    asm volatile(
        "mma.sync.aligned.m16n8k8.row.col.f32.tf32.tf32.f32 "
        "{%0,%1,%2,%3}, {%4,%5,%6,%7}, {%8,%9}, {%0,%1,%2,%3};"
        : "+f"(c[0]), "+f"(c[1]), "+f"(c[2]), "+f"(c[3])
        : "r"(a[0]), "r"(a[1]), "r"(a[2]), "r"(a[3]), "r"(b[0]), "r"(b[1]));
}

namespace {
struct ForkRes {
    cudaStream_t s1;
    cudaEvent_t e0, e1, e2;
    ForkRes() {
        cudaStreamCreateWithFlags(&s1, cudaStreamNonBlocking);
        cudaEventCreateWithFlags(&e0, cudaEventDisableTiming);
        cudaEventCreateWithFlags(&e1, cudaEventDisableTiming);
        cudaEventCreateWithFlags(&e2, cudaEventDisableTiming);
    }
};
ForkRes g_fork;
}

// ---------------------------------------------------------------------------
// CSR build: count (also zeroes lookback state) -> lookback scan -> scatter
// ---------------------------------------------------------------------------
__global__ void k_count(const int* __restrict__ dst, int* __restrict__ cnt,
                        unsigned long long* __restrict__ state, int E) {
    if (blockIdx.x == 0 && threadIdx.x < 64) state[threadIdx.x] = 0ULL;
    int e = blockIdx.x * blockDim.x + threadIdx.x;
    if (e < E) atomicAdd(&cnt[dst[e]], 1);
}

#define LB_INC (1ULL << 63)
#define LB_AGG (1ULL << 62)

// Decoupled-lookback exclusive scan over N counts (1024 thr/block, <=64 blocks,
// all co-resident on 148 SMs -> polling cannot deadlock).
__global__ void k_scanlb(const int* __restrict__ cnt,
                         unsigned long long* __restrict__ state,
                         int* __restrict__ row, int* __restrict__ cur,
                         int N, int E) {
    __shared__ int ws[32];
    __shared__ int s_prefix;
    const int b = blockIdx.x, tid = threadIdx.x;
    const int lane = tid & 31, wid = tid >> 5;
    const int i = b * 1024 + tid;

    int v = (i < N) ? cnt[i] : 0;
    int x = v;
#pragma unroll
    for (int o = 1; o < 32; o <<= 1) {
        int t = __shfl_up_sync(0xffffffffu, x, o);
        if (lane >= o) x += t;
    }
    if (lane == 31) ws[wid] = x;
    __syncthreads();
    if (wid == 0) {
        int y = ws[lane];
#pragma unroll
        for (int o = 1; o < 32; o <<= 1) {
            int t = __shfl_up_sync(0xffffffffu, y, o);
            if (lane >= o) y += t;
        }
        ws[lane] = y;
    }
    __syncthreads();
    const int blockTotal = ws[31];

    if (tid == 0) {
        if (b == 0) {
            atomicExch(&state[0], (unsigned long long)(unsigned)blockTotal | LB_INC);
            s_prefix = 0;
        } else {
            atomicExch(&state[b], (unsigned long long)(unsigned)blockTotal | LB_AGG);
            long long pre = 0;
            int j = b - 1;
            while (j >= 0) {
                unsigned long long s;
                do { s = atomicAdd(&state[j], 0ULL); } while ((s >> 62) == 0ULL);
                pre += (unsigned)(s & 0xffffffffu);
                if (s & LB_INC) break;
                j--;
            }
            atomicExch(&state[b],
                       (unsigned long long)(unsigned)(pre + blockTotal) | LB_INC);
            s_prefix = (int)pre;
        }
    }
    __syncthreads();

    int excl = s_prefix + (wid ? ws[wid - 1] : 0) + x - v;
    if (i < N) { row[i] = excl; cur[i] = excl; }
    if (i == 0) row[N] = E;
}

__global__ void k_scatter(const int* __restrict__ src, const int* __restrict__ dst,
                          int* __restrict__ cur, int* __restrict__ col, int E) {
    int e = blockIdx.x * blockDim.x + threadIdx.x;
    if (e >= E) return;
    int slot = atomicAdd(&cur[dst[e]], 1);
    col[slot] = src[e];
}
__global__ void k_wcat(const float* __restrict__ W2, const float* __restrict__ resW2,
                       float* __restrict__ Wc) {
    int i = blockIdx.x * blockDim.x + threadIdx.x;
    if (i >= 128 * 128) return;
    int k = i >> 7, j = i & 127;
    Wc[i] = (j < 64) ? W2[k * 64 + j] : resW2[k * 64 + (j - 64)];
}

// ---------------------------------------------------------------------------
// TF32 mma.sync GEMM + fused scores. stage ALIASES sW (dead after mainloop).
// ---------------------------------------------------------------------------
template <int K, int HS, bool SPLIT, bool EMB>
__global__ void __launch_bounds__(256)
k_mgemm(const float* __restrict__ A, const int* __restrict__ feats,
        const float* __restrict__ fv, const float* __restrict__ emb,
        const float* __restrict__ W,
        void* __restrict__ outh, float* __restrict__ out2,
        const float* __restrict__ al, const float* __restrict__ ar,
        float* __restrict__ el, float* __restrict__ er, int N) {
    extern __shared__ char smraw[];
    uint32_t* sW    = (uint32_t*)smraw;                    // K*132
    uint32_t* sA    = (uint32_t*)(smraw + K * 132 * 4);    // 64*(K+4)
    float*    stage = (float*)smraw;                       // aliases sW (64*132)
    constexpr int SAS = K + 4;

    const int tid = threadIdx.x;
    const int wid = tid >> 5, lane = tid & 31;
    const int g = lane >> 2, t = lane & 3;
    const int row0 = blockIdx.x * 64;
    const int wRow = (wid >> 2) * 32, wCol = (wid & 3) * 32;

    for (int i = tid; i < K * 32; i += 256) {
        int k = i >> 5, c4 = i & 31;
        float4 v = *(const float4*)&W[k * 128 + c4 * 4];
        uint4 u;
        u.x = f2tf32(v.x); u.y = f2tf32(v.y); u.z = f2tf32(v.z); u.w = f2tf32(v.w);
        *(uint4*)&sW[k * 132 + c4 * 4] = u;
    }
    constexpr int C4 = K / 4;
    for (int i = tid; i < 64 * C4; i += 256) {
        int r = i / C4, c4 = i % C4, rr = row0 + r;
        float4 v = make_float4(0.f, 0.f, 0.f, 0.f);
        if (rr < N) {
            if (EMB) {
                float s = fv[rr];
                v = *(const float4*)&emb[(long long)feats[rr] * 64 + c4 * 4];
                v.x *= s; v.y *= s; v.z *= s; v.w *= s;
            } else {
                v = *(const float4*)&A[(size_t)rr * K + c4 * 4];
            }
        }
        uint4 u;
        u.x = f2tf32(v.x); u.y = f2tf32(v.y); u.z = f2tf32(v.z); u.w = f2tf32(v.w);
        *(uint4*)&sA[r * SAS + c4 * 4] = u;
    }
    __syncthreads();

    float c[2][4][4];
#pragma unroll
    for (int mf = 0; mf < 2; mf++)
#pragma unroll
        for (int nf = 0; nf < 4; nf++)
#pragma unroll
            for (int i = 0; i < 4; i++) c[mf][nf][i] = 0.f;

#pragma unroll
    for (int ks = 0; ks < K / 8; ks++) {
        const int k0 = ks * 8;
        uint32_t a[2][4];
#pragma unroll
        for (int mf = 0; mf < 2; mf++) {
            int rb = wRow + mf * 16;
            a[mf][0] = sA[(rb + g)     * SAS + k0 + t];
            a[mf][1] = sA[(rb + g + 8) * SAS + k0 + t];
            a[mf][2] = sA[(rb + g)     * SAS + k0 + t + 4];
            a[mf][3] = sA[(rb + g + 8) * SAS + k0 + t + 4];
        }
        uint32_t b[4][2];
#pragma unroll
        for (int nf = 0; nf < 4; nf++) {
            int cc = wCol + nf * 8 + g;
            b[nf][0] = sW[(k0 + t)     * 132 + cc];
            b[nf][1] = sW[(k0 + t + 4) * 132 + cc];
        }
#pragma unroll
        for (int mf = 0; mf < 2; mf++)
#pragma unroll
            for (int nf = 0; nf < 4; nf++)
                mma_tf32(c[mf][nf], a[mf], b[nf]);
    }
    __syncthreads();   // sW dead; stage takes over

#pragma unroll
    for (int mf = 0; mf < 2; mf++) {
#pragma unroll
        for (int nf = 0; nf < 4; nf++) {
            int ra = wRow + mf * 16 + g;
            int cc = wCol + nf * 8 + t * 2;
            *(float2*)&stage[ra * 132 + cc]       = make_float2(c[mf][nf][0], c[mf][nf][1]);
            *(float2*)&stage[(ra + 8) * 132 + cc] = make_float2(c[mf][nf][2], c[mf][nf][3]);
        }
    }
    __syncthreads();

    float4 a4 = make_float4(0.f, 0.f, 0.f, 0.f);
    float4 r4 = make_float4(0.f, 0.f, 0.f, 0.f);
    if (lane * 4 < HS * 64) {
        a4 = *(const float4*)&al[lane * 4];
        r4 = *(const float4*)&ar[lane * 4];
    }
    __half* fhh = (__half*)outh;
#pragma unroll
    for (int q = 0; q < 8; q++) {
        int r = wid * 8 + q;
        int rr = row0 + r;
        float4 f = *(const float4*)&stage[r * 132 + lane * 4];
        float sl = f.x * a4.x + f.y * a4.y + f.z * a4.z + f.w * a4.w;
        float sr = f.x * r4.x + f.y * r4.y + f.z * r4.z + f.w * r4.w;
#pragma unroll
        for (int off = 8; off > 0; off >>= 1) {
            sl += __shfl_xor_sync(0xffffffffu, sl, off);
            sr += __shfl_xor_sync(0xffffffffu, sr, off);
        }
        int h = lane >> 4;
        if ((lane & 15) == 0 && h < HS && rr < N) {
            el[rr * HS + h] = sl;
            er[rr * HS + h] = sr;
        }
        if (rr < N) {
            __half2 ha = __float22half2_rn(make_float2(f.x, f.y));
            __half2 hb = __float22half2_rn(make_float2(f.z, f.w));
            uint2 u;
            u.x = *(uint32_t*)&ha; u.y = *(uint32_t*)&hb;
            if (SPLIT) {
                if (lane < 16) *(uint2*)(fhh + (size_t)rr * 64 + lane * 4) = u;
                else           *(float4*)&out2[(size_t)rr * 64 + lane * 4 - 64] = f;
            } else {
                *(uint2*)(fhh + (size_t)rr * 128 + lane * 4) = u;
            }
        }
    }
}

// ---------------------------------------------------------------------------
// R13 aggregation: warp per dst node; fp16 fh rows; L = O/8 lanes per row
// (uint4 per lane), G = 32/L edges in parallel; 2 banks.
// ---------------------------------------------------------------------------
template <int O, int H, bool ELU>
__global__ void __launch_bounds__(256)
k_aggr(const int* __restrict__ row, const int* __restrict__ col,
       const float* __restrict__ el, const float* __restrict__ er,
       const void* __restrict__ fhv, const float* __restrict__ bias,
       const float* __restrict__ res, float* __restrict__ out, int N) {
    constexpr int L = O / 8;     // 16 (O=128) or 8 (O=64)
    constexpr int G = 32 / L;    // 2 or 4
    const unsigned FULL = 0xffffffffu;
    int w    = (blockIdx.x * blockDim.x + threadIdx.x) >> 5;
    int lane = threadIdx.x & 31;
    if (w >= N) return;
    const int grp = lane / L, sub = lane % L;
    const int c0 = sub * 8;
    const bool topHead = (H == 2) && (c0 >= 64);
    const __half* fhh = (const __half*)fhv;

    const float er0 = er[w * H + 0];
    const float er1 = (H == 2) ? er[w * H + 1] : 0.f;
    const int e0 = row[w], e1 = row[w + 1];

    float den0 = 0.f, den1 = 0.f;
    float acc[2][8];
#pragma unroll
    for (int b = 0; b < 2; b++)
#pragma unroll
        for (int i = 0; i < 8; i++) acc[b][i] = 0.f;

    for (int base = e0; base < e1; base += 32) {
        int idx = base + lane;
        bool valid = idx < e1;
        int s_l = valid ? col[idx] : 0;
        float p0_l = 0.f, p1_l = 0.f;
        if (valid) {
            if (H == 2) {
                float2 ev = *(const float2*)&el[s_l * 2];
                p0_l = __expf(lrelu(ev.x + er0));
                p1_l = __expf(lrelu(ev.y + er1));
                den0 += p0_l; den1 += p1_l;
            } else {
                p0_l = __expf(lrelu(el[s_l] + er0));
                den0 += p0_l;
            }
        }
        int n = min(32, e1 - base);
        for (int j = 0; j < n; j += 2 * G) {
#pragma unroll
            for (int b = 0; b < 2; b++) {
                int srcLane = j + b * G + grp;
                int   s  = __shfl_sync(FULL, s_l,  srcLane);
                float pa = __shfl_sync(FULL, p0_l, srcLane);
                float p;
                if (H == 2) {
                    float pb = __shfl_sync(FULL, p1_l, srcLane);
                    p = topHead ? pb : pa;
                } else p = pa;
                uint4 u = *(const uint4*)(fhh + (size_t)s * O + c0);
                float2 f0 = __half22float2(*(__half2*)&u.x);
                float2 f1 = __half22float2(*(__half2*)&u.y);
                float2 f2 = __half22float2(*(__half2*)&u.z);
                float2 f3 = __half22float2(*(__half2*)&u.w);
                acc[b][0] += p * f0.x; acc[b][1] += p * f0.y;
                acc[b][2] += p * f1.x; acc[b][3] += p * f1.y;
                acc[b][4] += p * f2.x; acc[b][5] += p * f2.y;
                acc[b][6] += p * f3.x; acc[b][7] += p * f3.y;
            }
        }
    }

#pragma unroll
    for (int o = 16; o > 0; o >>= 1) {
        den0 += __shfl_xor_sync(FULL, den0, o);
        if (H == 2) den1 += __shfl_xor_sync(FULL, den1, o);
    }
    float sum[8];
#pragma unroll
    for (int i = 0; i < 8; i++) {
        float v = acc[0][i] + acc[1][i];
#pragma unroll
        for (int o = L; o < 32; o <<= 1) v += __shfl_xor_sync(FULL, v, o);
        sum[i] = v;
    }

    if (grp == 0) {
        float den = topHead ? den1 : den0;
        float inv = 1.f / fmaxf(den, 1e-9f);
        float4 bva = *(const float4*)&bias[c0];
        float4 bvb = *(const float4*)&bias[c0 + 4];
        float4 ra = make_float4(0.f, 0.f, 0.f, 0.f), rb = ra;
        if (res) {
            ra = *(const float4*)&res[(size_t)w * O + c0];
            rb = *(const float4*)&res[(size_t)w * O + c0 + 4];
        }
        float o8[8];
        o8[0] = sum[0] * inv + bva.x + ra.x;
        o8[1] = sum[1] * inv + bva.y + ra.y;
        o8[2] = sum[2] * inv + bva.z + ra.z;
        o8[3] = sum[3] * inv + bva.w + ra.w;
        o8[4] = sum[4] * inv + bvb.x + rb.x;
        o8[5] = sum[5] * inv + bvb.y + rb.y;
        o8[6] = sum[6] * inv + bvb.z + rb.z;
        o8[7] = sum[7] * inv + bvb.w + rb.w;
        if (ELU) {
#pragma unroll
            for (int i = 0; i < 8; i++)
                o8[i] = o8[i] > 0.f ? o8[i] : (__expf(o8[i]) - 1.f);
        }
        *(float4*)&out[(size_t)w * O + c0]     = make_float4(o8[0], o8[1], o8[2], o8[3]);
        *(float4*)&out[(size_t)w * O + c0 + 4] = make_float4(o8[4], o8[5], o8[6], o8[7]);
    }
}

// ---------------------------------------------------------------------------
extern "C" void kernel_launch(void* const* d_in, const int* in_sizes, int n_in,
                              void* d_out, int out_size) {
    const int*   feats = (const int*)  d_in[0];
    const float* fv    = (const float*)d_in[1];
    const int*   src   = (const int*)  d_in[2];
    const int*   dst   = (const int*)  d_in[3];
    const float* emb   = (const float*)d_in[4];
    const float* W0    = (const float*)d_in[5];
    const float* al0   = (const float*)d_in[6];
    const float* ar0   = (const float*)d_in[7];
    const float* b0    = (const float*)d_in[8];
    const float* W1    = (const float*)d_in[9];
    const float* al1   = (const float*)d_in[10];
    const float* ar1   = (const float*)d_in[11];
    const float* b1    = (const float*)d_in[12];
    const float* W2    = (const float*)d_in[13];
    const float* al2   = (const float*)d_in[14];
    const float* ar2   = (const float*)d_in[15];
    const float* b2    = (const float*)d_in[16];
    const float* resW2 = (const float*)d_in[17];
    float* out = (float*)d_out;

    const int N = in_sizes[0] / 8;
    const int E = in_sizes[2];

    float *hA, *hB, *fh, *el, *er, *Wc;
    int *row, *cur, *col;
    unsigned long long* state;
    cudaGetSymbolAddress((void**)&hA,    g_hA);
    cudaGetSymbolAddress((void**)&hB,    g_hB);
    cudaGetSymbolAddress((void**)&fh,    g_fh);
    cudaGetSymbolAddress((void**)&el,    g_el);
    cudaGetSymbolAddress((void**)&er,    g_er);
    cudaGetSymbolAddress((void**)&Wc,    g_Wc);
    cudaGetSymbolAddress((void**)&row,   g_row);
    cudaGetSymbolAddress((void**)&cur,   g_cur);
    cudaGetSymbolAddress((void**)&col,   g_col);
    cudaGetSymbolAddress((void**)&state, g_state);

    const int TB = 256;
    const int gB = (N + 63) / 64;
    const int aggrBlocks = (N * 32 + TB - 1) / TB;
    const int nb = (N + 1023) / 1024;

    const int SM64  = 64 * 132 * 4  + 64 * (64 + 4)  * 4;   // 51200
    const int SM128 = 128 * 132 * 4 + 64 * (128 + 4) * 4;   // 101376
    cudaFuncSetAttribute(k_mgemm<64, 2, false, true>,
                         cudaFuncAttributeMaxDynamicSharedMemorySize, SM64);
    cudaFuncSetAttribute(k_mgemm<128, 2, false, false>,
                         cudaFuncAttributeMaxDynamicSharedMemorySize, SM128);
    cudaFuncSetAttribute(k_mgemm<128, 1, true, false>,
                         cudaFuncAttributeMaxDynamicSharedMemorySize, SM128);

    cudaStream_t s1 = g_fork.s1;

    // fork: CSR build on s1; GEMM0 (fused embedding) on main
    cudaEventRecord(g_fork.e0, 0);
    cudaStreamWaitEvent(s1, g_fork.e0, 0);

    cudaMemsetAsync(cur, 0, (size_t)N * sizeof(int), s1);
    k_count  <<<(E + TB - 1) / TB, TB, 0, s1>>>(dst, cur, state, E);
    k_scanlb <<<nb, 1024, 0, s1>>>(cur, state, row, cur, N, E);
    k_scatter<<<(E + TB - 1) / TB, TB, 0, s1>>>(src, dst, cur, col, E);
    cudaEventRecord(g_fork.e1, s1);              // gates aggr0
    k_wcat<<<(128 * 128 + TB - 1) / TB, TB, 0, s1>>>(W2, resW2, Wc);
    cudaEventRecord(g_fork.e2, s1);              // gates GEMM2

    // Layer 0 GEMM with fused embedding (main)
    k_mgemm<64, 2, false, true><<<gB, 256, SM64>>>(
        nullptr, feats, fv, emb, W0, fh, nullptr, al0, ar0, el, er, N);

    cudaStreamWaitEvent(0, g_fork.e1, 0);

    // Layer 0 aggregation -> hB (fp32)
    k_aggr<128, 2, true><<<aggrBlocks, TB>>>(row, col, el, er, fh, b0, nullptr, hB, N);

    // Layer 1
    k_mgemm<128, 2, false, false><<<gB, 256, SM128>>>(
        hB, nullptr, nullptr, nullptr, W1, fh, nullptr, al1, ar1, el, er, N);
    k_aggr<128, 2, true><<<aggrBlocks, TB>>>(row, col, el, er, fh, b1, hB, hA, N);

    // Layer 2: combined [W2|resW2]; fh(half, cols 0-63) + residual hB(f32)
    cudaStreamWaitEvent(0, g_fork.e2, 0);
    k_mgemm<128, 1, true, false><<<gB, 256, SM128>>>(
        hA, nullptr, nullptr, nullptr, Wc, fh, hB, al2, ar2, el, er, N);
    k_aggr<64, 1, false><<<aggrBlocks, TB>>>(row, col, el, er, fh, b2, hB, out, N);
}

// round 16
// speedup vs baseline: 1.1422x; 1.0542x over previous
#include <cuda_runtime.h>
#include <cuda_fp16.h>
#include <cstdint>

// ---------------------------------------------------------------------------
// 3-layer GAT, N=50000 nodes, E=800000 edges.
// R16: R15 (best: 217us) + fp16 inter-layer activations: aggr writes half,
//      GEMM A-loader reads half->tf32, aggr-1 residual reads half. Layer-2
//      projected residual and final output remain fp32.
// ---------------------------------------------------------------------------

#define NMAX 50000
#define EMAX 800000

__device__ float g_hA[NMAX * 128];   // half storage for layer-1 output
__device__ float g_hB[NMAX * 128];   // half (layer-0 out) then fp32 (layer-2 residual)
__device__ float g_fh[NMAX * 128];   // half fh
__device__ float g_el[NMAX * 2];
__device__ float g_er[NMAX * 2];
__device__ float g_Wc[128 * 128];
__device__ int   g_row[NMAX + 1];
__device__ int   g_cur[NMAX];
__device__ int   g_col[EMAX];
__device__ unsigned long long g_state[64];

__device__ __forceinline__ float lrelu(float v) { return v > 0.f ? v : 0.2f * v; }

__device__ __forceinline__ uint32_t f2tf32(float f) {
    uint32_t r;
    asm("cvt.rna.tf32.f32 %0, %1;" : "=r"(r) : "f"(f));
    return r;
}

__device__ __forceinline__ void mma_tf32(float c[4], const uint32_t a[4],
                                         const uint32_t b[2]) {
    asm volatile(
        "mma.sync.aligned.m16n8k8.row.col.f32.tf32.tf32.f32 "
        "{%0,%1,%2,%3}, {%4,%5,%6,%7}, {%8,%9}, {%0,%1,%2,%3};"
        : "+f"(c[0]), "+f"(c[1]), "+f"(c[2]), "+f"(c[3])
        : "r"(a[0]), "r"(a[1]), "r"(a[2]), "r"(a[3]), "r"(b[0]), "r"(b[1]));
}

namespace {
struct ForkRes {
    cudaStream_t s1;
    cudaEvent_t e0, e1, e2;
    ForkRes() {
        cudaStreamCreateWithFlags(&s1, cudaStreamNonBlocking);
        cudaEventCreateWithFlags(&e0, cudaEventDisableTiming);
        cudaEventCreateWithFlags(&e1, cudaEventDisableTiming);
        cudaEventCreateWithFlags(&e2, cudaEventDisableTiming);
    }
};
ForkRes g_fork;
}

// ---------------------------------------------------------------------------
// CSR build: count (zeroes lookback state) -> lookback scan -> scatter
// ---------------------------------------------------------------------------
__global__ void k_count(const int* __restrict__ dst, int* __restrict__ cnt,
                        unsigned long long* __restrict__ state, int E) {
    if (blockIdx.x == 0 && threadIdx.x < 64) state[threadIdx.x] = 0ULL;
    int e = blockIdx.x * blockDim.x + threadIdx.x;
    if (e < E) atomicAdd(&cnt[dst[e]], 1);
}

#define LB_INC (1ULL << 63)
#define LB_AGG (1ULL << 62)

__global__ void k_scanlb(const int* __restrict__ cnt,
                         unsigned long long* __restrict__ state,
                         int* __restrict__ row, int* __restrict__ cur,
                         int N, int E) {
    __shared__ int ws[32];
    __shared__ int s_prefix;
    const int b = blockIdx.x, tid = threadIdx.x;
    const int lane = tid & 31, wid = tid >> 5;
    const int i = b * 1024 + tid;

    int v = (i < N) ? cnt[i] : 0;
    int x = v;
#pragma unroll
    for (int o = 1; o < 32; o <<= 1) {
        int t = __shfl_up_sync(0xffffffffu, x, o);
        if (lane >= o) x += t;
    }
    if (lane == 31) ws[wid] = x;
    __syncthreads();
    if (wid == 0) {
        int y = ws[lane];
#pragma unroll
        for (int o = 1; o < 32; o <<= 1) {
            int t = __shfl_up_sync(0xffffffffu, y, o);
            if (lane >= o) y += t;
        }
        ws[lane] = y;
    }
    __syncthreads();
    const int blockTotal = ws[31];

    if (tid == 0) {
        if (b == 0) {
            atomicExch(&state[0], (unsigned long long)(unsigned)blockTotal | LB_INC);
            s_prefix = 0;
        } else {
            atomicExch(&state[b], (unsigned long long)(unsigned)blockTotal | LB_AGG);
            long long pre = 0;
            int j = b - 1;
            while (j >= 0) {
                unsigned long long s;
                do { s = atomicAdd(&state[j], 0ULL); } while ((s >> 62) == 0ULL);
                pre += (unsigned)(s & 0xffffffffu);
                if (s & LB_INC) break;
                j--;
            }
            atomicExch(&state[b],
                       (unsigned long long)(unsigned)(pre + blockTotal) | LB_INC);
            s_prefix = (int)pre;
        }
    }
    __syncthreads();

    int excl = s_prefix + (wid ? ws[wid - 1] : 0) + x - v;
    if (i < N) { row[i] = excl; cur[i] = excl; }
    if (i == 0) row[N] = E;
}

__global__ void k_scatter(const int* __restrict__ src, const int* __restrict__ dst,
                          int* __restrict__ cur, int* __restrict__ col, int E) {
    int e = blockIdx.x * blockDim.x + threadIdx.x;
    if (e >= E) return;
    int slot = atomicAdd(&cur[dst[e]], 1);
    col[slot] = src[e];
}
__global__ void k_wcat(const float* __restrict__ W2, const float* __restrict__ resW2,
                       float* __restrict__ Wc) {
    int i = blockIdx.x * blockDim.x + threadIdx.x;
    if (i >= 128 * 128) return;
    int k = i >> 7, j = i & 127;
    Wc[i] = (j < 64) ? W2[k * 64 + j] : resW2[k * 64 + (j - 64)];
}

// ---------------------------------------------------------------------------
// TF32 mma.sync GEMM + fused scores. stage ALIASES sW.
// AH: A input stored as __half. EMB: A gathered from emb table (fp32).
// ---------------------------------------------------------------------------
template <int K, int HS, bool SPLIT, bool EMB, bool AH>
__global__ void __launch_bounds__(256)
k_mgemm(const void* __restrict__ Av, const int* __restrict__ feats,
        const float* __restrict__ fv, const float* __restrict__ emb,
        const float* __restrict__ W,
        void* __restrict__ outh, float* __restrict__ out2,
        const float* __restrict__ al, const float* __restrict__ ar,
        float* __restrict__ el, float* __restrict__ er, int N) {
    extern __shared__ char smraw[];
    uint32_t* sW    = (uint32_t*)smraw;                    // K*132
    uint32_t* sA    = (uint32_t*)(smraw + K * 132 * 4);    // 64*(K+4)
    float*    stage = (float*)smraw;                       // aliases sW
    constexpr int SAS = K + 4;

    const int tid = threadIdx.x;
    const int wid = tid >> 5, lane = tid & 31;
    const int g = lane >> 2, t = lane & 3;
    const int row0 = blockIdx.x * 64;
    const int wRow = (wid >> 2) * 32, wCol = (wid & 3) * 32;

    for (int i = tid; i < K * 32; i += 256) {
        int k = i >> 5, c4 = i & 31;
        float4 v = *(const float4*)&W[k * 128 + c4 * 4];
        uint4 u;
        u.x = f2tf32(v.x); u.y = f2tf32(v.y); u.z = f2tf32(v.z); u.w = f2tf32(v.w);
        *(uint4*)&sW[k * 132 + c4 * 4] = u;
    }
    constexpr int C4 = K / 4;
    for (int i = tid; i < 64 * C4; i += 256) {
        int r = i / C4, c4 = i % C4, rr = row0 + r;
        float4 v = make_float4(0.f, 0.f, 0.f, 0.f);
        if (rr < N) {
            if (EMB) {
                float s = fv[rr];
                v = *(const float4*)&emb[(long long)feats[rr] * 64 + c4 * 4];
                v.x *= s; v.y *= s; v.z *= s; v.w *= s;
            } else if (AH) {
                const __half* Ah = (const __half*)Av;
                uint2 hv = *(const uint2*)(Ah + (size_t)rr * K + c4 * 4);
                float2 lo = __half22float2(*(__half2*)&hv.x);
                float2 hi = __half22float2(*(__half2*)&hv.y);
                v = make_float4(lo.x, lo.y, hi.x, hi.y);
            } else {
                v = *(const float4*)((const float*)Av + (size_t)rr * K + c4 * 4);
            }
        }
        uint4 u;
        u.x = f2tf32(v.x); u.y = f2tf32(v.y); u.z = f2tf32(v.z); u.w = f2tf32(v.w);
        *(uint4*)&sA[r * SAS + c4 * 4] = u;
    }
    __syncthreads();

    float c[2][4][4];
#pragma unroll
    for (int mf = 0; mf < 2; mf++)
#pragma unroll
        for (int nf = 0; nf < 4; nf++)
#pragma unroll
            for (int i = 0; i < 4; i++) c[mf][nf][i] = 0.f;

#pragma unroll
    for (int ks = 0; ks < K / 8; ks++) {
        const int k0 = ks * 8;
        uint32_t a[2][4];
#pragma unroll
        for (int mf = 0; mf < 2; mf++) {
            int rb = wRow + mf * 16;
            a[mf][0] = sA[(rb + g)     * SAS + k0 + t];
            a[mf][1] = sA[(rb + g + 8) * SAS + k0 + t];
            a[mf][2] = sA[(rb + g)     * SAS + k0 + t + 4];
            a[mf][3] = sA[(rb + g + 8) * SAS + k0 + t + 4];
        }
        uint32_t b[4][2];
#pragma unroll
        for (int nf = 0; nf < 4; nf++) {
            int cc = wCol + nf * 8 + g;
            b[nf][0] = sW[(k0 + t)     * 132 + cc];
            b[nf][1] = sW[(k0 + t + 4) * 132 + cc];
        }
#pragma unroll
        for (int mf = 0; mf < 2; mf++)
#pragma unroll
            for (int nf = 0; nf < 4; nf++)
                mma_tf32(c[mf][nf], a[mf], b[nf]);
    }
    __syncthreads();   // sW dead; stage takes over

#pragma unroll
    for (int mf = 0; mf < 2; mf++) {
#pragma unroll
        for (int nf = 0; nf < 4; nf++) {
            int ra = wRow + mf * 16 + g;
            int cc = wCol + nf * 8 + t * 2;
            *(float2*)&stage[ra * 132 + cc]       = make_float2(c[mf][nf][0], c[mf][nf][1]);
            *(float2*)&stage[(ra + 8) * 132 + cc] = make_float2(c[mf][nf][2], c[mf][nf][3]);
        }
    }
    __syncthreads();

    float4 a4 = make_float4(0.f, 0.f, 0.f, 0.f);
    float4 r4 = make_float4(0.f, 0.f, 0.f, 0.f);
    if (lane * 4 < HS * 64) {
        a4 = *(const float4*)&al[lane * 4];
        r4 = *(const float4*)&ar[lane * 4];
    }
    __half* fhh = (__half*)outh;
#pragma unroll
    for (int q = 0; q < 8; q++) {
        int r = wid * 8 + q;
        int rr = row0 + r;
        float4 f = *(const float4*)&stage[r * 132 + lane * 4];
        float sl = f.x * a4.x + f.y * a4.y + f.z * a4.z + f.w * a4.w;
        float sr = f.x * r4.x + f.y * r4.y + f.z * r4.z + f.w * r4.w;
#pragma unroll
        for (int off = 8; off > 0; off >>= 1) {
            sl += __shfl_xor_sync(0xffffffffu, sl, off);
            sr += __shfl_xor_sync(0xffffffffu, sr, off);
        }
        int h = lane >> 4;
        if ((lane & 15) == 0 && h < HS && rr < N) {
            el[rr * HS + h] = sl;
            er[rr * HS + h] = sr;
        }
        if (rr < N) {
            __half2 ha = __float22half2_rn(make_float2(f.x, f.y));
            __half2 hb = __float22half2_rn(make_float2(f.z, f.w));
            uint2 u;
            u.x = *(uint32_t*)&ha; u.y = *(uint32_t*)&hb;
            if (SPLIT) {
                if (lane < 16) *(uint2*)(fhh + (size_t)rr * 64 + lane * 4) = u;
                else           *(float4*)&out2[(size_t)rr * 64 + lane * 4 - 64] = f;
            } else {
                *(uint2*)(fhh + (size_t)rr * 128 + lane * 4) = u;
            }
        }
    }
}

// ---------------------------------------------------------------------------
// Aggregation (R13 2-bank core): warp per dst node; fp16 fh rows.
// RESH: residual stored as half. OUTH: write output as half.
// ---------------------------------------------------------------------------
template <int O, int H, bool ELU, bool RESH, bool OUTH>
__global__ void __launch_bounds__(256)
k_aggr(const int* __restrict__ row, const int* __restrict__ col,
       const float* __restrict__ el, const float* __restrict__ er,
       const void* __restrict__ fhv, const float* __restrict__ bias,
       const void* __restrict__ resv, void* __restrict__ outv, int N) {
    constexpr int L = O / 8;     // 16 (O=128) or 8 (O=64)
    constexpr int G = 32 / L;    // 2 or 4
    const unsigned FULL = 0xffffffffu;
    int w    = (blockIdx.x * blockDim.x + threadIdx.x) >> 5;
    int lane = threadIdx.x & 31;
    if (w >= N) return;
    const int grp = lane / L, sub = lane % L;
    const int c0 = sub * 8;
    const bool topHead = (H == 2) && (c0 >= 64);
    const __half* fhh = (const __half*)fhv;

    const float er0 = er[w * H + 0];
    const float er1 = (H == 2) ? er[w * H + 1] : 0.f;
    const int e0 = row[w], e1 = row[w + 1];

    float den0 = 0.f, den1 = 0.f;
    float acc[2][8];
#pragma unroll
    for (int b = 0; b < 2; b++)
#pragma unroll
        for (int i = 0; i < 8; i++) acc[b][i] = 0.f;

    for (int base = e0; base < e1; base += 32) {
        int idx = base + lane;
        bool valid = idx < e1;
        int s_l = valid ? col[idx] : 0;
        float p0_l = 0.f, p1_l = 0.f;
        if (valid) {
            if (H == 2) {
                float2 ev = *(const float2*)&el[s_l * 2];
                p0_l = __expf(lrelu(ev.x + er0));
                p1_l = __expf(lrelu(ev.y + er1));
                den0 += p0_l; den1 += p1_l;
            } else {
                p0_l = __expf(lrelu(el[s_l] + er0));
                den0 += p0_l;
            }
        }
        int n = min(32, e1 - base);
        for (int j = 0; j < n; j += 2 * G) {
#pragma unroll
            for (int b = 0; b < 2; b++) {
                int srcLane = j + b * G + grp;
                int   s  = __shfl_sync(FULL, s_l,  srcLane);
                float pa = __shfl_sync(FULL, p0_l, srcLane);
                float p;
                if (H == 2) {
                    float pb = __shfl_sync(FULL, p1_l, srcLane);
                    p = topHead ? pb : pa;
                } else p = pa;
                uint4 u = *(const uint4*)(fhh + (size_t)s * O + c0);
                float2 f0 = __half22float2(*(__half2*)&u.x);
                float2 f1 = __half22float2(*(__half2*)&u.y);
                float2 f2 = __half22float2(*(__half2*)&u.z);
                float2 f3 = __half22float2(*(__half2*)&u.w);
                acc[b][0] += p * f0.x; acc[b][1] += p * f0.y;
                acc[b][2] += p * f1.x; acc[b][3] += p * f1.y;
                acc[b][4] += p * f2.x; acc[b][5] += p * f2.y;
                acc[b][6] += p * f3.x; acc[b][7] += p * f3.y;
            }
        }
    }

#pragma unroll
    for (int o = 16; o > 0; o >>= 1) {
        den0 += __shfl_xor_sync(FULL, den0, o);
        if (H == 2) den1 += __shfl_xor_sync(FULL, den1, o);
    }
    float sum[8];
#pragma unroll
    for (int i = 0; i < 8; i++) {
        float v = acc[0][i] + acc[1][i];
#pragma unroll
        for (int o = L; o < 32; o <<= 1) v += __shfl_xor_sync(FULL, v, o);
        sum[i] = v;
    }

    if (grp == 0) {
        float den = topHead ? den1 : den0;
        float inv = 1.f / fmaxf(den, 1e-9f);
        float4 bva = *(const float4*)&bias[c0];
        float4 bvb = *(const float4*)&bias[c0 + 4];
        float r8[8];
#pragma unroll
        for (int i = 0; i < 8; i++) r8[i] = 0.f;
        if (resv) {
            if (RESH) {
                const __half* rh = (const __half*)resv;
                uint4 u = *(const uint4*)(rh + (size_t)w * O + c0);
                float2 f0 = __half22float2(*(__half2*)&u.x);
                float2 f1 = __half22float2(*(__half2*)&u.y);
                float2 f2 = __half22float2(*(__half2*)&u.z);
                float2 f3 = __half22float2(*(__half2*)&u.w);
                r8[0] = f0.x; r8[1] = f0.y; r8[2] = f1.x; r8[3] = f1.y;
                r8[4] = f2.x; r8[5] = f2.y; r8[6] = f3.x; r8[7] = f3.y;
            } else {
                const float* rf = (const float*)resv;
                float4 ra = *(const float4*)&rf[(size_t)w * O + c0];
                float4 rb = *(const float4*)&rf[(size_t)w * O + c0 + 4];
                r8[0] = ra.x; r8[1] = ra.y; r8[2] = ra.z; r8[3] = ra.w;
                r8[4] = rb.x; r8[5] = rb.y; r8[6] = rb.z; r8[7] = rb.w;
            }
        }
        float o8[8];
        o8[0] = sum[0] * inv + bva.x + r8[0];
        o8[1] = sum[1] * inv + bva.y + r8[1];
        o8[2] = sum[2] * inv + bva.z + r8[2];
        o8[3] = sum[3] * inv + bva.w + r8[3];
        o8[4] = sum[4] * inv + bvb.x + r8[4];
        o8[5] = sum[5] * inv + bvb.y + r8[5];
        o8[6] = sum[6] * inv + bvb.z + r8[6];
        o8[7] = sum[7] * inv + bvb.w + r8[7];
        if (ELU) {
#pragma unroll
            for (int i = 0; i < 8; i++)
                o8[i] = o8[i] > 0.f ? o8[i] : (__expf(o8[i]) - 1.f);
        }
        if (OUTH) {
            __half* oh = (__half*)outv;
            __half2 h0 = __float22half2_rn(make_float2(o8[0], o8[1]));
            __half2 h1 = __float22half2_rn(make_float2(o8[2], o8[3]));
            __half2 h2 = __float22half2_rn(make_float2(o8[4], o8[5]));
            __half2 h3 = __float22half2_rn(make_float2(o8[6], o8[7]));
            uint4 u;
            u.x = *(uint32_t*)&h0; u.y = *(uint32_t*)&h1;
            u.z = *(uint32_t*)&h2; u.w = *(uint32_t*)&h3;
            *(uint4*)(oh + (size_t)w * O + c0) = u;
        } else {
            float* of = (float*)outv;
            *(float4*)&of[(size_t)w * O + c0]     = make_float4(o8[0], o8[1], o8[2], o8[3]);
            *(float4*)&of[(size_t)w * O + c0 + 4] = make_float4(o8[4], o8[5], o8[6], o8[7]);
        }
    }
}

// ---------------------------------------------------------------------------
extern "C" void kernel_launch(void* const* d_in, const int* in_sizes, int n_in,
                              void* d_out, int out_size) {
    const int*   feats = (const int*)  d_in[0];
    const float* fv    = (const float*)d_in[1];
    const int*   src   = (const int*)  d_in[2];
    const int*   dst   = (const int*)  d_in[3];
    const float* emb   = (const float*)d_in[4];
    const float* W0    = (const float*)d_in[5];
    const float* al0   = (const float*)d_in[6];
    const float* ar0   = (const float*)d_in[7];
    const float* b0    = (const float*)d_in[8];
    const float* W1    = (const float*)d_in[9];
    const float* al1   = (const float*)d_in[10];
    const float* ar1   = (const float*)d_in[11];
    const float* b1    = (const float*)d_in[12];
    const float* W2    = (const float*)d_in[13];
    const float* al2   = (const float*)d_in[14];
    const float* ar2   = (const float*)d_in[15];
    const float* b2    = (const float*)d_in[16];
    const float* resW2 = (const float*)d_in[17];
    float* out = (float*)d_out;

    const int N = in_sizes[0] / 8;
    const int E = in_sizes[2];

    float *hA, *hB, *fh, *el, *er, *Wc;
    int *row, *cur, *col;
    unsigned long long* state;
    cudaGetSymbolAddress((void**)&hA,    g_hA);
    cudaGetSymbolAddress((void**)&hB,    g_hB);
    cudaGetSymbolAddress((void**)&fh,    g_fh);
    cudaGetSymbolAddress((void**)&el,    g_el);
    cudaGetSymbolAddress((void**)&er,    g_er);
    cudaGetSymbolAddress((void**)&Wc,    g_Wc);
    cudaGetSymbolAddress((void**)&row,   g_row);
    cudaGetSymbolAddress((void**)&cur,   g_cur);
    cudaGetSymbolAddress((void**)&col,   g_col);
    cudaGetSymbolAddress((void**)&state, g_state);

    const int TB = 256;
    const int gB = (N + 63) / 64;
    const int aggrBlocks = (N * 32 + TB - 1) / TB;
    const int nb = (N + 1023) / 1024;

    const int SM64  = 64 * 132 * 4  + 64 * (64 + 4)  * 4;   // 51200
    const int SM128 = 128 * 132 * 4 + 64 * (128 + 4) * 4;   // 101376
    cudaFuncSetAttribute(k_mgemm<64, 2, false, true, false>,
                         cudaFuncAttributeMaxDynamicSharedMemorySize, SM64);
    cudaFuncSetAttribute(k_mgemm<128, 2, false, false, true>,
                         cudaFuncAttributeMaxDynamicSharedMemorySize, SM128);
    cudaFuncSetAttribute(k_mgemm<128, 1, true, false, true>,
                         cudaFuncAttributeMaxDynamicSharedMemorySize, SM128);

    cudaStream_t s1 = g_fork.s1;

    // fork: CSR build on s1; GEMM0 (fused embedding) on main
    cudaEventRecord(g_fork.e0, 0);
    cudaStreamWaitEvent(s1, g_fork.e0, 0);

    cudaMemsetAsync(cur, 0, (size_t)N * sizeof(int), s1);
    k_count  <<<(E + TB - 1) / TB, TB, 0, s1>>>(dst, cur, state, E);
    k_scanlb <<<nb, 1024, 0, s1>>>(cur, state, row, cur, N, E);
    k_scatter<<<(E + TB - 1) / TB, TB, 0, s1>>>(src, dst, cur, col, E);
    cudaEventRecord(g_fork.e1, s1);              // gates aggr0
    k_wcat<<<(128 * 128 + TB - 1) / TB, TB, 0, s1>>>(W2, resW2, Wc);
    cudaEventRecord(g_fork.e2, s1);              // gates GEMM2

    // Layer 0 GEMM with fused embedding (main)
    k_mgemm<64, 2, false, true, false><<<gB, 256, SM64>>>(
        nullptr, feats, fv, emb, W0, fh, nullptr, al0, ar0, el, er, N);

    cudaStreamWaitEvent(0, g_fork.e1, 0);

    // Layer 0 aggregation -> hB (half)
    k_aggr<128, 2, true, false, true><<<aggrBlocks, TB>>>(
        row, col, el, er, fh, b0, nullptr, hB, N);

    // Layer 1: A = hB (half); residual = hB (half); out -> hA (half)
    k_mgemm<128, 2, false, false, true><<<gB, 256, SM128>>>(
        hB, nullptr, nullptr, nullptr, W1, fh, nullptr, al1, ar1, el, er, N);
    k_aggr<128, 2, true, true, true><<<aggrBlocks, TB>>>(
        row, col, el, er, fh, b1, hB, hA, N);

    // Layer 2: A = hA (half); combined [W2|resW2] -> fh(half) + residual hB(f32)
    cudaStreamWaitEvent(0, g_fork.e2, 0);
    k_mgemm<128, 1, true, false, true><<<gB, 256, SM128>>>(
        hA, nullptr, nullptr, nullptr, Wc, fh, hB, al2, ar2, el, er, N);
    k_aggr<64, 1, false, false, false><<<aggrBlocks, TB>>>(
        row, col, el, er, fh, b2, hB, out, N);
}